// round 1
// baseline (speedup 1.0000x reference)
#include <cuda_runtime.h>
#include <stdint.h>

#define BATCH 32
#define CIN   128
#define HH    56
#define WW    56
#define COUT  256

// ---------------- scratch (device globals: no allocations allowed) ----------
__device__ int8_t   g_qx[BATCH*HH*WW*CIN];   // NHWC int8, ~12.85 MB
__device__ int8_t   g_qw[9*32*COUT*4];       // [tap][k][co][r], r = ci%4 (packed for dp4a)
__device__ unsigned g_amax_x, g_amax_w;
__device__ float    g_scale_x, g_scale_w, g_dq;

// ---------------- 0: reset (graph replays must be deterministic) ------------
__global__ void k_reset() { g_amax_x = 0u; g_amax_w = 0u; }

// ---------------- 1: amax reduction (exact: max is order-independent) -------
__global__ void k_amax(const float4* __restrict__ p, int n4, int which) {
    float m = 0.f;
    for (int i = blockIdx.x*blockDim.x + threadIdx.x; i < n4; i += gridDim.x*blockDim.x) {
        float4 v = p[i];
        m = fmaxf(m, fmaxf(fmaxf(fabsf(v.x), fabsf(v.y)),
                           fmaxf(fabsf(v.z), fabsf(v.w))));
    }
    #pragma unroll
    for (int o = 16; o; o >>= 1) m = fmaxf(m, __shfl_xor_sync(0xffffffffu, m, o));
    __shared__ float sm[32];
    int lane = threadIdx.x & 31, w = threadIdx.x >> 5;
    if (lane == 0) sm[w] = m;
    __syncthreads();
    if (w == 0) {
        m = (lane < (int)(blockDim.x >> 5)) ? sm[lane] : 0.f;
        #pragma unroll
        for (int o = 16; o; o >>= 1) m = fmaxf(m, __shfl_xor_sync(0xffffffffu, m, o));
        if (lane == 0) {
            unsigned* tgt = which ? &g_amax_w : &g_amax_x;
            atomicMax(tgt, __float_as_uint(m));
        }
    }
}

// ---------------- 2: scales (fp32 IEEE div to match reference) --------------
__global__ void k_scales() {
    float ax = __uint_as_float(g_amax_x), aw = __uint_as_float(g_amax_w);
    float sx = __fdiv_rn(127.0f, ax);
    float sw = __fdiv_rn(127.0f, aw);
    g_scale_x = sx; g_scale_w = sw;
    g_dq = __fdiv_rn(1.0f, __fmul_rn(sx, sw));
}

// ---------------- 3: quantize x, NCHW -> NHWC via smem transpose ------------
// one block per (b, h) row: read coalesced over w, write coalesced over c
__global__ void k_quant_x(const float* __restrict__ x) {
    __shared__ int8_t s[CIN][60];   // pad 56->60: transposed reads hit distinct banks
    int bh = blockIdx.x;
    int b = bh / HH, h = bh % HH;
    float sc = g_scale_x;
    const float* base = x + ((size_t)b*CIN*HH + h)*WW;   // + c*HH*WW + w
    for (int e = threadIdx.x; e < CIN*WW; e += blockDim.x) {
        int c = e / WW, w = e - c*WW;
        float q = rintf(base[(size_t)c*HH*WW + w] * sc);   // round half-to-even
        q = fminf(fmaxf(q, -127.f), 127.f);
        s[c][w] = (int8_t)q;
    }
    __syncthreads();
    int8_t* dst = g_qx + ((size_t)(b*HH + h) * WW) * CIN;
    for (int e = threadIdx.x; e < CIN*WW; e += blockDim.x) {
        int w = e >> 7, c = e & 127;   // e = w*128 + c : consecutive c => coalesced
        dst[e] = s[c][w];
    }
}

// ---------------- 4: quantize w into [tap][k][co][r] packed layout ----------
__global__ void k_quant_w(const float* __restrict__ wt) {
    float sc = g_scale_w;
    const int n = 9*32*COUT*4;
    for (int o = blockIdx.x*blockDim.x + threadIdx.x; o < n; o += gridDim.x*blockDim.x) {
        int r   = o & 3;
        int co  = (o >> 2)  & 255;
        int k   = (o >> 10) & 31;
        int tap = o >> 15;
        int ci  = k*4 + r;
        float q = rintf(wt[(co*CIN + ci)*9 + tap] * sc);
        q = fminf(fmaxf(q, -127.f), 127.f);
        g_qw[o] = (int8_t)q;
    }
}

// ---------------- 5: int8 conv, dp4a, 8px x 8cout register blocking ---------
// block = 128 threads = 8 pixel-rows x 16 cout-groups; tile 8x8 spatial,
// 128 couts per block (grid.z = b*2 + coutHalf)
__global__ void __launch_bounds__(128) k_conv(const float* __restrict__ bias,
                                              float* __restrict__ out) {
    __shared__ int s_x[32][10][12];   // [k][ph][pw pad->12] : conflict-free reads
    __shared__ int s_w[32][128];      // [k][co] : co-group reads hit distinct banks

    int bx = blockIdx.x, by = blockIdx.y, bz = blockIdx.z;
    int b = bz >> 1, coBase = (bz & 1) << 7;
    int tid = threadIdx.x;
    int py = tid & 7;          // pixel row within tile
    int cg = tid >> 3;         // cout group (8 couts each)
    int gx0 = bx*8, gy0 = by*8;

    // stage input patch 10x10x128 (with pad=1 halo), coalesced over k
    const int* qx = (const int*)g_qx;
    for (int idx = tid; idx < 3200; idx += 128) {
        int k = idx & 31, pos = idx >> 5;
        int ph = pos / 10, pw = pos - ph*10;
        int gh = gy0 + ph - 1, gw = gx0 + pw - 1;
        int v = 0;
        if ((unsigned)gh < 56u && (unsigned)gw < 56u)
            v = qx[((b*56 + gh)*56 + gw)*32 + k];
        s_x[k][ph][pw] = v;
    }

    int acc[8][8];
    #pragma unroll
    for (int j = 0; j < 8; j++)
        #pragma unroll
        for (int c = 0; c < 8; c++) acc[j][c] = 0;

    const int* qw = (const int*)g_qw;
    for (int tap = 0; tap < 9; tap++) {
        __syncthreads();   // also covers s_x stores on first iteration
        const int* wsrc = qw + tap*32*256 + coBase;
        for (int idx = tid; idx < 4096; idx += 128) {
            int k = idx >> 7, co = idx & 127;
            s_w[k][co] = wsrc[k*256 + co];
        }
        __syncthreads();
        int kh = tap / 3, kw = tap - kh*3;
        #pragma unroll 4
        for (int k = 0; k < 32; k++) {
            int xv[8], wv[8];
            #pragma unroll
            for (int j = 0; j < 8; j++) xv[j] = s_x[k][py + kh][j + kw];
            #pragma unroll
            for (int c = 0; c < 8; c++) wv[c] = s_w[k][cg*8 + c];
            #pragma unroll
            for (int j = 0; j < 8; j++)
                #pragma unroll
                for (int c = 0; c < 8; c++)
                    acc[j][c] = __dp4a(xv[j], wv[c], acc[j][c]);
        }
    }

    // epilogue: dequant + bias, vectorized float4 stores (NCHW out)
    float dq = g_dq;
    int gy = gy0 + py;
    #pragma unroll
    for (int c = 0; c < 8; c++) {
        int co = coBase + cg*8 + c;
        float bv = bias[co];
        float t[8];
        #pragma unroll
        for (int j = 0; j < 8; j++) t[j] = (float)acc[j][c] * dq + bv;
        float* op = out + (((size_t)b*COUT + co)*HH + gy)*WW + gx0;
        ((float4*)op)[0] = make_float4(t[0], t[1], t[2], t[3]);
        ((float4*)op)[1] = make_float4(t[4], t[5], t[6], t[7]);
    }
}

// ---------------- launch -----------------------------------------------------
extern "C" void kernel_launch(void* const* d_in, const int* in_sizes, int n_in,
                              void* d_out, int out_size) {
    const float* x    = (const float*)d_in[0];
    const float* wt   = (const float*)d_in[1];
    const float* bias = (const float*)d_in[2];
    float* out = (float*)d_out;

    const int nx  = BATCH*CIN*HH*WW;     // 12,845,056 (div by 4)
    const int nw  = COUT*CIN*3*3;        // 294,912   (div by 4)

    k_reset<<<1, 1>>>();
    k_amax<<<1024, 256>>>((const float4*)x,  nx/4, 0);
    k_amax<<<288,  256>>>((const float4*)wt, nw/4, 1);
    k_scales<<<1, 1>>>();
    k_quant_x<<<BATCH*HH, 256>>>(x);
    k_quant_w<<<288, 256>>>(wt);
    dim3 grid(WW/8, HH/8, BATCH*2);
    k_conv<<<grid, 128>>>(bias, out);
    (void)in_sizes; (void)n_in; (void)out_size;
}

// round 3
// speedup vs baseline: 1.0902x; 1.0902x over previous
#include <cuda_runtime.h>
#include <stdint.h>

#define BATCH 32
#define CIN   128
#define HH    56
#define WW    56
#define COUT  256
#define HP    58
#define NPIX  (HH*WW)            // 3136
#define IMGB  (HP*HP*CIN)

// ---------------- scratch (device globals) ----------------------------------
__device__ int8_t   g_qx[BATCH*HP*HP*CIN];   // padded NHWC int8
__device__ int8_t   g_qw[9*COUT*CIN];        // [tap][co][ci]
__device__ unsigned g_amax_x, g_amax_w;
__device__ float    g_scale_x, g_scale_w, g_dq;

// ---------------- helpers -----------------------------------------------------
__device__ __forceinline__ uint32_t smem_u32(const void* p) {
    uint32_t a;
    asm("{ .reg .u64 t; cvta.to.shared.u64 t, %1; cvt.u32.u64 %0, t; }" : "=r"(a) : "l"(p));
    return a;
}
#define SW128(o) ((o) ^ (((o) >> 3) & 0x70))

__device__ __forceinline__ void cp16(uint32_t dst, const void* src) {
    asm volatile("cp.async.cg.shared.global [%0], [%1], 16;" :: "r"(dst), "l"(src) : "memory");
}
#define CP_COMMIT()  asm volatile("cp.async.commit_group;" ::: "memory")
#define CP_WAIT(n)   asm volatile("cp.async.wait_group %0;" :: "n"(n) : "memory")

__device__ __forceinline__ unsigned lds32(uint32_t a) {
    unsigned v; asm volatile("ld.shared.b32 %0, [%1];" : "=r"(v) : "r"(a)); return v;
}

__device__ __forceinline__ void mma16832(int* d, const unsigned* a, const unsigned* b) {
    asm volatile("mma.sync.aligned.m16n8k32.row.col.s32.s8.s8.s32 "
        "{%0,%1,%2,%3}, {%4,%5,%6,%7}, {%8,%9}, {%0,%1,%2,%3};"
        : "+r"(d[0]), "+r"(d[1]), "+r"(d[2]), "+r"(d[3])
        : "r"(a[0]), "r"(a[1]), "r"(a[2]), "r"(a[3]), "r"(b[0]), "r"(b[1]));
}

// ---------------- 0: reset ----------------------------------------------------
__global__ void k_reset() { g_amax_x = 0u; g_amax_w = 0u; }

// ---------------- 1: amax -----------------------------------------------------
__global__ void k_amax(const float4* __restrict__ p, int n4, int which) {
    float m = 0.f;
    for (int i = blockIdx.x*blockDim.x + threadIdx.x; i < n4; i += gridDim.x*blockDim.x) {
        float4 v = p[i];
        m = fmaxf(m, fmaxf(fmaxf(fabsf(v.x), fabsf(v.y)), fmaxf(fabsf(v.z), fabsf(v.w))));
    }
    #pragma unroll
    for (int o = 16; o; o >>= 1) m = fmaxf(m, __shfl_xor_sync(0xffffffffu, m, o));
    __shared__ float sm[32];
    int lane = threadIdx.x & 31, w = threadIdx.x >> 5;
    if (lane == 0) sm[w] = m;
    __syncthreads();
    if (w == 0) {
        m = (lane < (int)(blockDim.x >> 5)) ? sm[lane] : 0.f;
        #pragma unroll
        for (int o = 16; o; o >>= 1) m = fmaxf(m, __shfl_xor_sync(0xffffffffu, m, o));
        if (lane == 0) atomicMax(which ? &g_amax_w : &g_amax_x, __float_as_uint(m));
    }
}

// ---------------- 2: scales ---------------------------------------------------
__global__ void k_scales() {
    float sx = __fdiv_rn(127.0f, __uint_as_float(g_amax_x));
    float sw = __fdiv_rn(127.0f, __uint_as_float(g_amax_w));
    g_scale_x = sx; g_scale_w = sw;
    g_dq = __fdiv_rn(1.0f, __fmul_rn(sx, sw));
}

// ---------------- 3: quantize x into padded NHWC ------------------------------
__global__ void k_quant_x(const float* __restrict__ x) {
    int b = blockIdx.x / HP, hp = blockIdx.x % HP;
    int8_t* dst = g_qx + ((size_t)b*HP + hp)*HP*CIN;
    if (hp == 0 || hp == HP-1) {
        for (int e = threadIdx.x; e < HP*CIN/16; e += blockDim.x)
            ((int4*)dst)[e] = make_int4(0,0,0,0);
        return;
    }
    int h = hp - 1;
    __shared__ int8_t s[CIN][60];
    float sc = g_scale_x;
    const float* base = x + ((size_t)b*CIN*HH + h)*WW;
    for (int e = threadIdx.x; e < CIN*WW; e += blockDim.x) {
        int c = e / WW, w = e - c*WW;
        float q = rintf(base[(size_t)c*HH*WW + w] * sc);
        q = fminf(fmaxf(q, -127.f), 127.f);
        s[c][w] = (int8_t)q;
    }
    __syncthreads();
    for (int e = threadIdx.x; e < HP*CIN; e += blockDim.x) {
        int wp = e >> 7, c = e & 127;
        dst[e] = (wp == 0 || wp == HP-1) ? (int8_t)0 : s[c][wp-1];
    }
}

// ---------------- 4: quantize w into [tap][co][ci] ----------------------------
__global__ void k_quant_w(const float* __restrict__ wt) {
    float sc = g_scale_w;
    const int n = 9*COUT*CIN;
    for (int o = blockIdx.x*blockDim.x + threadIdx.x; o < n; o += gridDim.x*blockDim.x) {
        int ci  = o & 127;
        int co  = (o >> 7) & 255;
        int tap = o >> 15;
        float q = rintf(wt[(co*CIN + ci)*9 + tap] * sc);
        q = fminf(fmaxf(q, -127.f), 127.f);
        g_qw[o] = (int8_t)q;
    }
}

// ---------------- 5: int8 implicit-GEMM conv via mma.sync (IMMA) --------------
// CTA: 128 pixels x 128 couts. 8 warps = 4(m) x 2(n); warp tile 32px x 64co.
// K = 9 taps x 128ci; per-tap stage: A 16KB + B 16KB, cp.async double-buffered.
#define STAGE_B 32768
#define SMEM_TOTAL (2*STAGE_B)

__global__ void __launch_bounds__(256, 2) k_conv(const float* __restrict__ bias,
                                                 float* __restrict__ out) {
    extern __shared__ char smem[];
    uint32_t sb = smem_u32(smem);
    float* s_out = (float*)smem;

    int tid = tid = threadIdx.x;
    int wid = tid >> 5, lane = tid & 31;
    int wm = wid & 3, wn = wid >> 2;          // 4 x 2 warp grid
    int g = lane >> 2, tg = lane & 3;

    int tile  = blockIdx.x;                   // 0..24
    int coBase = blockIdx.y << 7;             // 0 or 128
    int bimg  = blockIdx.z;
    int p0 = tile * 128;

    // ---- per-thread producer coords (4 A rows + 4 B rows, 16B each) ----
    int tg8 = tid >> 3, j16 = (tid & 7) * 16;
    int aoff[4];
    #pragma unroll
    for (int k = 0; k < 4; k++) {
        int p = min(p0 + k*32 + tg8, NPIX-1);
        int h = p / WW, w = p - h*WW;
        aoff[k] = (h*HP + w)*CIN + j16;       // unpadded h,w + halo offset later
    }
    const int8_t* qb = g_qx + (size_t)bimg * IMGB;
    int wrow = tg8;                            // B stage row within [0,128)
    const int8_t* wb = g_qw + (coBase + wrow)*CIN + j16;

    int acc[2][8][4];
    #pragma unroll
    for (int mt = 0; mt < 2; mt++)
        #pragma unroll
        for (int nt = 0; nt < 8; nt++)
            #pragma unroll
            for (int r = 0; r < 4; r++) acc[mt][nt][r] = 0;

    // ---- prefetch chunk 0 ----
    {
        uint32_t stgA = sb, stgB = sb + 16384;
        #pragma unroll
        for (int k = 0; k < 4; k++) {
            cp16(stgA + SW128((k*32 + tg8)*128 + j16), qb + aoff[k]);           // dh=dw=0
            cp16(stgB + SW128((k*32 + tg8)*128 + j16), wb + (size_t)k*32*CIN);
        }
        CP_COMMIT();
    }

    for (int ch = 0; ch < 9; ch++) {
        int st = ch & 1;
        if (ch < 8) {
            int nc = ch + 1;
            int dh = nc / 3, dw = nc - dh*3;
            int doff = (dh*HP + dw)*CIN;
            uint32_t stgA = sb + ((nc & 1) ? STAGE_B : 0), stgB = stgA + 16384;
            const int8_t* wsrc = wb + (size_t)nc*COUT*CIN;
            #pragma unroll
            for (int k = 0; k < 4; k++) {
                cp16(stgA + SW128((k*32 + tg8)*128 + j16), qb + aoff[k] + doff);
                cp16(stgB + SW128((k*32 + tg8)*128 + j16), wsrc + (size_t)k*32*CIN);
            }
            CP_COMMIT();
            CP_WAIT(1);
        } else {
            CP_WAIT(0);
        }
        __syncthreads();

        uint32_t stgA = sb + st*STAGE_B, stgB = stgA + 16384;
        #pragma unroll
        for (int ks = 0; ks < 4; ks++) {
            unsigned bf[8][2];
            #pragma unroll
            for (int nt = 0; nt < 8; nt++) {
                uint32_t base = (wn*64 + nt*8 + g)*128 + ks*32 + tg*4;
                bf[nt][0] = lds32(stgB + SW128(base));
                bf[nt][1] = lds32(stgB + SW128(base + 16));
            }
            #pragma unroll
            for (int mt = 0; mt < 2; mt++) {
                unsigned af[4];
                uint32_t base = (wm*32 + mt*16 + g)*128 + ks*32 + tg*4;
                af[0] = lds32(stgA + SW128(base));
                af[1] = lds32(stgA + SW128(base + 8*128));
                af[2] = lds32(stgA + SW128(base + 16));
                af[3] = lds32(stgA + SW128(base + 8*128 + 16));
                #pragma unroll
                for (int nt = 0; nt < 8; nt++)
                    mma16832(acc[mt][nt], af, bf[nt]);
            }
        }
        __syncthreads();
    }

    // ---- epilogue: stage [64co][132px] in smem, coalesced dequant+bias stores ----
    float dq = g_dq;
    int rr = tid >> 7;              // 0..1
    int px = tid & 127;
    bool pv = (p0 + px) < NPIX;
    float* obase = out + ((size_t)bimg*COUT + coBase)*NPIX + p0 + px;

    #pragma unroll
    for (int pass = 0; pass < 2; pass++) {
        if (wn == pass) {
            #pragma unroll
            for (int mt = 0; mt < 2; mt++) {
                int px0 = wm*32 + mt*16 + g;
                #pragma unroll
                for (int nt = 0; nt < 8; nt++) {
                    int cl = nt*8 + tg*2;
                    s_out[cl*132 + px0]           = (float)acc[mt][nt][0] * dq;
                    s_out[(cl+1)*132 + px0]       = (float)acc[mt][nt][1] * dq;
                    s_out[cl*132 + px0 + 8]       = (float)acc[mt][nt][2] * dq;
                    s_out[(cl+1)*132 + px0 + 8]   = (float)acc[mt][nt][3] * dq;
                }
            }
        }
        __syncthreads();
        if (pv) {
            #pragma unroll 8
            for (int it = 0; it < 32; it++) {
                int row = it*2 + rr;
                int co = pass*64 + row;
                obase[(size_t)co * NPIX] = s_out[row*132 + px] + __ldg(&bias[coBase + co]);
            }
        }
        __syncthreads();
    }
}

// ---------------- launch ------------------------------------------------------
extern "C" void kernel_launch(void* const* d_in, const int* in_sizes, int n_in,
                              void* d_out, int out_size) {
    const float* x    = (const float*)d_in[0];
    const float* wt   = (const float*)d_in[1];
    const float* bias = (const float*)d_in[2];
    float* out = (float*)d_out;

    const int nx = BATCH*CIN*HH*WW;
    const int nw = COUT*CIN*9;

    cudaFuncSetAttribute(k_conv, cudaFuncAttributeMaxDynamicSharedMemorySize, SMEM_TOTAL);

    k_reset<<<1, 1>>>();
    k_amax<<<1024, 256>>>((const float4*)x,  nx/4, 0);
    k_amax<<<288,  256>>>((const float4*)wt, nw/4, 1);
    k_scales<<<1, 1>>>();
    k_quant_x<<<BATCH*HP, 256>>>(x);
    k_quant_w<<<288, 256>>>(wt);
    dim3 grid(25, 2, BATCH);
    k_conv<<<grid, 256, SMEM_TOTAL>>>(bias, out);
    (void)in_sizes; (void)n_in; (void)out_size;
}